// round 2
// baseline (speedup 1.0000x reference)
#include <cuda_runtime.h>
#include <math.h>

#define VOCAB 8192
#define N_TOK 8192
#define INTER 4352
#define EMB   512

// ---------------- scratch (static __device__ — no allocations allowed) ----------------
__device__ __align__(16) float g_At[(size_t)INTER * N_TOK];   // A^T: [K=inter][M=ntok]
__device__ __align__(16) float g_h2[(size_t)N_TOK * EMB];     // h2 pre-BN2: [M][N]
__device__ __align__(16) int   g_cnt[VOCAB];                  // histogram of x_t
__device__ __align__(16) int   g_xt[N_TOK];                   // normalized int32 indices
__device__ int   g_is64;                                      // 1 if input x_t is int64
__device__ __align__(16) float g_p1[64 * EMB];                // partial sums for BN2 stats
__device__ __align__(16) float g_p2[64 * EMB];
__device__ float g_mul2[EMB];
__device__ float g_add2[EMB];

// ---------------- helpers ----------------
__device__ __forceinline__ float gelu_exact(float x) {
    return 0.5f * x * (1.0f + erff(x * 0.7071067811865476f));
}

__device__ __forceinline__ unsigned long long pack2(float lo, float hi) {
    unsigned long long r;
    asm("mov.b64 %0, {%1, %2};" : "=l"(r) : "f"(lo), "f"(hi));
    return r;
}
__device__ __forceinline__ void unpack2(unsigned long long v, float& lo, float& hi) {
    asm("mov.b64 {%0, %1}, %2;" : "=f"(lo), "=f"(hi) : "l"(v));
}
// packed dual-FMA: d.lo += a.lo*b.lo ; d.hi += a.hi*b.hi  (SASS FFMA2, PTX-only path)
__device__ __forceinline__ void ffma2(unsigned long long& d, unsigned long long a, unsigned long long b) {
    asm("fma.rn.f32x2 %0, %1, %2, %0;" : "+l"(d) : "l"(a), "l"(b));
}

// ---------------- K0a: dtype detect. Reads ONLY first N_TOK int32 words, which is
// exactly the int32-buffer size (safe under both layouts). For int64 input
// (values < 8192, little-endian) every odd word is 0. ----------------
__global__ void detect_k(const int* __restrict__ xt_raw) {
    __shared__ int nz;
    if (threadIdx.x == 0) nz = 0;
    __syncthreads();
    int any = 0;
    for (int i = threadIdx.x; i < N_TOK / 2; i += 1024)
        any |= (xt_raw[2 * i + 1] != 0);
    if (any) atomicOr(&nz, 1);
    __syncthreads();
    if (threadIdx.x == 0) g_is64 = (nz == 0);
}

// ---------------- K0b: normalize indices + zero histogram ----------------
__global__ void normalize_k(const int* __restrict__ xt_raw) {
    int n = blockIdx.x * 256 + threadIdx.x;
    int v = g_is64 ? xt_raw[2 * n] : xt_raw[n];
    g_xt[n] = v;
    g_cnt[n] = 0;     // N_TOK == VOCAB, zero histogram in same launch
}

// ---------------- K2: histogram of x_t ----------------
__global__ void hist_k() {
    int v = g_xt[blockIdx.x * 256 + threadIdx.x];
    atomicAdd(&g_cnt[v], 1);
}

// ---------------- K3: fused gather + BN1 + gelu -> At (one block per channel i) ----
__global__ __launch_bounds__(256) void gather_bn1_k(
    const float* __restrict__ W1,
    const float* __restrict__ g1, const float* __restrict__ beta1)
{
    __shared__ __align__(16) float row[VOCAB];     // 32 KB: one row of W1
    __shared__ float red[16];
    const int i   = blockIdx.x;
    const int tid = threadIdx.x;
    const float* wrow = W1 + (size_t)i * VOCAB;

    // load row coalesced + accumulate histogram-weighted stats in the same pass
    float s1 = 0.f, s2 = 0.f;
    for (int idx = tid; idx < VOCAB / 4; idx += 256) {
        float4 w = reinterpret_cast<const float4*>(wrow)[idx];
        int4   c = reinterpret_cast<const int4*>(g_cnt)[idx];
        reinterpret_cast<float4*>(row)[idx] = w;
        s1 += (float)c.x * w.x + (float)c.y * w.y + (float)c.z * w.z + (float)c.w * w.w;
        s2 += (float)c.x * w.x * w.x + (float)c.y * w.y * w.y
            + (float)c.z * w.z * w.z + (float)c.w * w.w * w.w;
    }
    // block reduce
    #pragma unroll
    for (int o = 16; o > 0; o >>= 1) {
        s1 += __shfl_down_sync(0xffffffffu, s1, o);
        s2 += __shfl_down_sync(0xffffffffu, s2, o);
    }
    if ((tid & 31) == 0) { red[tid >> 5] = s1; red[8 + (tid >> 5)] = s2; }
    __syncthreads();

    float t1 = 0.f, t2 = 0.f;
    #pragma unroll
    for (int w = 0; w < 8; w++) { t1 += red[w]; t2 += red[8 + w]; }
    const float mean = t1 * (1.f / (float)N_TOK);
    const float var  = t2 * (1.f / (float)N_TOK) - mean * mean;
    const float mul  = g1[i] * rsqrtf(var + 1e-5f);
    const float beta = beta1[i];

    float* dst = g_At + (size_t)i * N_TOK;
    for (int n = tid; n < N_TOK; n += 256) {
        int c = g_xt[n];                          // L2-resident, coalesced
        float x = (row[c] - mean) * mul + beta;
        dst[n] = gelu_exact(x);
    }
}

// ---------------- K4: GEMM  h2[m,n] = sum_k At[k,m]*W2[n,k] + b2[n] --------------
// BM=128, BN=64, BK=16, 256 threads, each thread: 8(m, packed pairs) x 4(n strided)
#define BM 128
#define BN 64
#define BK 16

__global__ __launch_bounds__(256) void gemm_k(
    const float* __restrict__ W2, const float* __restrict__ b2)
{
    __shared__ __align__(16) float As[BK][BM];                  // 8 KB
    __shared__ __align__(16) unsigned long long Bs[BK][BN + 1]; // pre-duplicated (b,b)
    const int tid = threadIdx.x;
    const int tx  = tid & 15;        // n-group
    const int ty  = tid >> 4;        // m-group
    const int m0  = blockIdx.y * BM;
    const int n0  = blockIdx.x * BN;

    unsigned long long acc[4][4];
    #pragma unroll
    for (int i = 0; i < 4; i++)
        #pragma unroll
        for (int j = 0; j < 4; j++) acc[i][j] = 0ull;

    for (int k0 = 0; k0 < INTER; k0 += BK) {
        // load A tile: At[k0+k][m0+m], coalesced float4 (2048 floats / 256 thr)
        #pragma unroll
        for (int r = 0; r < 2; r++) {
            int idx = tid + r * 256;          // 0..511 float4 slots
            int k = idx >> 5;                 // 16 k rows
            int m = (idx & 31) << 2;          // 128 m cols
            *reinterpret_cast<float4*>(&As[k][m]) =
                *reinterpret_cast<const float4*>(&g_At[(size_t)(k0 + k) * N_TOK + m0 + m]);
        }
        // load B tile: W2[n0+n][k0+k], duplicate into packed pairs
        {
            int n = tid >> 2;
            int k = (tid & 3) << 2;
            float4 v = *reinterpret_cast<const float4*>(&W2[(size_t)(n0 + n) * INTER + k0 + k]);
            Bs[k + 0][n] = pack2(v.x, v.x);
            Bs[k + 1][n] = pack2(v.y, v.y);
            Bs[k + 2][n] = pack2(v.z, v.z);
            Bs[k + 3][n] = pack2(v.w, v.w);
        }
        __syncthreads();

        #pragma unroll
        for (int k = 0; k < BK; k++) {
            unsigned long long ap[4], bp[4];
            #pragma unroll
            for (int i = 0; i < 4; i++)       // m pairs (broadcast across tx)
                ap[i] = *reinterpret_cast<const unsigned long long*>(&As[k][ty * 8 + 2 * i]);
            #pragma unroll
            for (int j = 0; j < 4; j++)       // n strided by 16 -> conflict-free LDS.64
                bp[j] = Bs[k][tx + 16 * j];
            #pragma unroll
            for (int j = 0; j < 4; j++)
                #pragma unroll
                for (int i = 0; i < 4; i++)
                    ffma2(acc[i][j], ap[i], bp[j]);
        }
        __syncthreads();
    }

    // epilogue: + bias, write [m][n]
    #pragma unroll
    for (int j = 0; j < 4; j++) {
        int n = n0 + tx + 16 * j;
        float bias = b2[n];
        #pragma unroll
        for (int i = 0; i < 4; i++) {
            float lo, hi;
            unpack2(acc[i][j], lo, hi);
            int m = m0 + ty * 8 + 2 * i;
            g_h2[(size_t)m * EMB + n]       = lo + bias;
            g_h2[(size_t)(m + 1) * EMB + n] = hi + bias;
        }
    }
}

// ---------------- K5: BN2 partial stats (deterministic, no atomics) --------------
__global__ __launch_bounds__(512) void stats_partial_k() {
    const int e = threadIdx.x;            // 512 channels
    const int b = blockIdx.x;             // 64 row blocks of 128
    float s1 = 0.f, s2 = 0.f;
    const float* base = g_h2 + (size_t)b * 128 * EMB + e;
    #pragma unroll 4
    for (int n = 0; n < 128; n++) {
        float v = base[(size_t)n * EMB];
        s1 += v;
        s2 += v * v;
    }
    g_p1[b * EMB + e] = s1;
    g_p2[b * EMB + e] = s2;
}

// ---------------- K6: finalize BN2 scale/shift ----------------
__global__ __launch_bounds__(512) void stats_final_k(
    const float* __restrict__ g2, const float* __restrict__ beta2)
{
    const int e = threadIdx.x;
    float s1 = 0.f, s2 = 0.f;
    #pragma unroll
    for (int b = 0; b < 64; b++) { s1 += g_p1[b * EMB + e]; s2 += g_p2[b * EMB + e]; }
    float m = s1 * (1.f / (float)N_TOK);
    float v = s2 * (1.f / (float)N_TOK) - m * m;
    float mul = g2[e] * rsqrtf(v + 1e-5f);
    g_mul2[e] = mul;
    g_add2[e] = beta2[e] - mul * m;
}

// ---------------- K7: BN2 apply + gelu -> out ----------------
__global__ __launch_bounds__(256) void final_k(float* __restrict__ out) {
    int idx = blockIdx.x * 256 + threadIdx.x;
    int e = idx & (EMB - 1);
    float x = fmaf(g_mul2[e], g_h2[idx], g_add2[e]);
    out[idx] = gelu_exact(x);
}

// ---------------- launch ----------------
extern "C" void kernel_launch(void* const* d_in, const int* in_sizes, int n_in,
                              void* d_out, int out_size)
{
    const int*   x_t_raw = (const int*)d_in[0];   // int32 OR int64 buffer; detected on-device
    const float* W1    = (const float*)d_in[1];
    // d_in[2] = b1 : cancels inside BN1 (mean includes it) -> unused
    const float* g1    = (const float*)d_in[3];
    const float* beta1 = (const float*)d_in[4];
    const float* W2    = (const float*)d_in[5];
    const float* b2    = (const float*)d_in[6];
    const float* g2    = (const float*)d_in[7];
    const float* beta2 = (const float*)d_in[8];
    float* out = (float*)d_out;

    detect_k<<<1, 1024>>>(x_t_raw);
    normalize_k<<<N_TOK / 256, 256>>>(x_t_raw);
    hist_k<<<N_TOK / 256, 256>>>();
    gather_bn1_k<<<INTER, 256>>>(W1, g1, beta1);
    gemm_k<<<dim3(EMB / BN, N_TOK / BM), 256>>>(W2, b2);
    stats_partial_k<<<64, 512>>>();
    stats_final_k<<<1, 512>>>(g2, beta2);
    final_k<<<(N_TOK * EMB) / 256, 256>>>(out);
}

// round 5
// speedup vs baseline: 4.8550x; 4.8550x over previous
#include <cuda_runtime.h>
#include <math.h>
#include <stdint.h>

#define VOCAB 8192
#define N_TOK 8192
#define INTER 4352
#define EMB   512

// ---------------- scratch (static __device__ — no allocations allowed) ----------------
__device__ __align__(16) float g_At[(size_t)INTER * N_TOK];   // A^T: [K][M], tf32-rounded
__device__ __align__(16) float g_W2r[(size_t)EMB * INTER];    // W2 tf32-rounded
__device__ __align__(16) float g_h2[(size_t)N_TOK * EMB];     // h2 pre-BN2: [M][N]
__device__ __align__(16) int   g_cnt[VOCAB];
__device__ __align__(16) int   g_xt[N_TOK];
__device__ int   g_is64;
__device__ __align__(16) float g_p1[64 * EMB];
__device__ __align__(16) float g_p2[64 * EMB];
__device__ float g_mul2[EMB];
__device__ float g_add2[EMB];

// ---------------- helpers ----------------
__device__ __forceinline__ float gelu_exact(float x) {
    return 0.5f * x * (1.0f + erff(x * 0.7071067811865476f));
}
__device__ __forceinline__ float rnd_tf32(float x) {
    unsigned u;
    asm("cvt.rna.tf32.f32 %0, %1;" : "=r"(u) : "f"(x));
    return __uint_as_float(u);
}
__device__ __forceinline__ uint32_t smem_u32(const void* p) {
    uint32_t a;
    asm("{ .reg .u64 t; cvta.to.shared.u64 t, %1; cvt.u32.u64 %0, t; }" : "=r"(a) : "l"(p));
    return a;
}
__device__ __forceinline__ void cp_async16(uint32_t dst, const void* src) {
    asm volatile("cp.async.cg.shared.global [%0], [%1], 16;" :: "r"(dst), "l"(src));
}
#define CP_COMMIT() asm volatile("cp.async.commit_group;" ::: "memory")
#define CP_WAIT(n)  asm volatile("cp.async.wait_group %0;" :: "n"(n) : "memory")

__device__ __forceinline__ void mma_tf32(float* d, const uint32_t* a, const uint32_t* b) {
    asm volatile(
        "mma.sync.aligned.m16n8k8.row.col.f32.tf32.tf32.f32 "
        "{%0,%1,%2,%3}, {%4,%5,%6,%7}, {%8,%9}, {%0,%1,%2,%3};"
        : "+f"(d[0]), "+f"(d[1]), "+f"(d[2]), "+f"(d[3])
        : "r"(a[0]), "r"(a[1]), "r"(a[2]), "r"(a[3]), "r"(b[0]), "r"(b[1]));
}

// ---------------- K0a: dtype detect (int32 vs int64 x_t buffer) ----------------
__global__ void detect_k(const int* __restrict__ xt_raw) {
    __shared__ int nz;
    if (threadIdx.x == 0) nz = 0;
    __syncthreads();
    int any = 0;
    for (int i = threadIdx.x; i < N_TOK / 2; i += 1024)
        any |= (xt_raw[2 * i + 1] != 0);
    if (any) atomicOr(&nz, 1);
    __syncthreads();
    if (threadIdx.x == 0) g_is64 = (nz == 0);
}

// ---------------- K0b: normalize indices + zero histogram ----------------
__global__ void normalize_k(const int* __restrict__ xt_raw) {
    int n = blockIdx.x * 256 + threadIdx.x;
    int v = g_is64 ? xt_raw[2 * n] : xt_raw[n];
    g_xt[n] = v;
    g_cnt[n] = 0;
}

// ---------------- K2: histogram ----------------
__global__ void hist_k() {
    int v = g_xt[blockIdx.x * 256 + threadIdx.x];
    atomicAdd(&g_cnt[v], 1);
}

// ---------------- K3: fused gather + BN1 + gelu -> At[k][m] (tf32-rounded) -------
__global__ __launch_bounds__(256) void gather_bn1_k(
    const float* __restrict__ W1,
    const float* __restrict__ g1, const float* __restrict__ beta1)
{
    __shared__ __align__(16) float row[VOCAB];
    __shared__ float red[16];
    const int i   = blockIdx.x;
    const int tid = threadIdx.x;
    const float* wrow = W1 + (size_t)i * VOCAB;

    float s1 = 0.f, s2 = 0.f;
    for (int idx = tid; idx < VOCAB / 4; idx += 256) {
        float4 w = reinterpret_cast<const float4*>(wrow)[idx];
        int4   c = reinterpret_cast<const int4*>(g_cnt)[idx];
        reinterpret_cast<float4*>(row)[idx] = w;
        s1 += (float)c.x * w.x + (float)c.y * w.y + (float)c.z * w.z + (float)c.w * w.w;
        s2 += (float)c.x * w.x * w.x + (float)c.y * w.y * w.y
            + (float)c.z * w.z * w.z + (float)c.w * w.w * w.w;
    }
    #pragma unroll
    for (int o = 16; o > 0; o >>= 1) {
        s1 += __shfl_down_sync(0xffffffffu, s1, o);
        s2 += __shfl_down_sync(0xffffffffu, s2, o);
    }
    if ((tid & 31) == 0) { red[tid >> 5] = s1; red[8 + (tid >> 5)] = s2; }
    __syncthreads();

    float t1 = 0.f, t2 = 0.f;
    #pragma unroll
    for (int w = 0; w < 8; w++) { t1 += red[w]; t2 += red[8 + w]; }
    const float mean = t1 * (1.f / (float)N_TOK);
    const float var  = t2 * (1.f / (float)N_TOK) - mean * mean;
    const float mul  = g1[i] * rsqrtf(var + 1e-5f);
    const float beta = beta1[i];

    float* dst = g_At + (size_t)i * N_TOK;
    #pragma unroll 4
    for (int n = tid; n < N_TOK; n += 256) {
        int c = g_xt[n];
        float x = (row[c] - mean) * mul + beta;
        dst[n] = rnd_tf32(gelu_exact(x));
    }
}

// ---------------- K3b: round W2 to tf32 ----------------
__global__ void round_w2_k(const float* __restrict__ W2) {
    int i = blockIdx.x * 256 + threadIdx.x;
    g_W2r[i] = rnd_tf32(W2[i]);
}

// ---------------- K4: mma.sync tf32 GEMM  h2[m][n] = sum_k At[k][m]*W2r[n][k] + b2
// BM=128, BN=128, BK=16, 256 thr (8 warps 2x4, warp tile 64x32), 4-stage cp.async
#define BK 16
#define NSTAGE (INTER / BK)                 // 272
#define A_WORDS (BK * 128)                  // 2048 floats, XOR-swizzled rows
#define B_WORDS (128 * 20)                  // 2560 floats, stride-20 rows
#define A_STAGE_BYTES (A_WORDS * 4)         // 8192
#define B_STAGE_BYTES (B_WORDS * 4)         // 10240
#define B_BASE_BYTES  (4 * A_STAGE_BYTES)   // Bs after 4 A stages
#define GEMM_SMEM (4 * (A_STAGE_BYTES + B_STAGE_BYTES))   // 73728

__device__ __forceinline__ void gemm_issue(uint32_t sb, int s, int m0, int n0, int tid) {
    const int k0  = s * BK;
    const int buf = s & 3;
    // A tile: 512 float4 (16 k-rows x 128 m), 2 per thread, XOR swizzle
    #pragma unroll
    for (int t = 0; t < 2; t++) {
        int idx = tid + t * 256;
        int k = idx >> 5;                 // 0..15
        int mq = (idx & 31) << 2;         // m in steps of 4
        const float* src = g_At + (size_t)(k0 + k) * N_TOK + m0 + mq;
        uint32_t word = (uint32_t)(k * 128 + (mq ^ (k << 3)));
        cp_async16(sb + buf * A_STAGE_BYTES + (word << 2), src);
    }
    // B tile: 512 float4 (128 n-rows x 16 k), 2 per thread, stride-20 rows
    #pragma unroll
    for (int t = 0; t < 2; t++) {
        int idx = tid + t * 256;
        int n = idx >> 2;                 // 0..127
        int kq = (idx & 3) << 2;          // k in steps of 4
        const float* src = g_W2r + (size_t)(n0 + n) * INTER + k0 + kq;
        uint32_t word = (uint32_t)(n * 20 + kq);
        cp_async16(sb + B_BASE_BYTES + buf * B_STAGE_BYTES + (word << 2), src);
    }
    CP_COMMIT();
}

__global__ __launch_bounds__(256, 2) void gemm_mma_k(const float* __restrict__ b2) {
    extern __shared__ __align__(16) char smem[];
    const uint32_t sb = smem_u32(smem);
    const uint32_t* As = reinterpret_cast<const uint32_t*>(smem);
    const uint32_t* Bs = reinterpret_cast<const uint32_t*>(smem + B_BASE_BYTES);

    const int tid    = threadIdx.x;
    const int lane   = tid & 31;
    const int wid    = tid >> 5;
    const int warp_m = wid & 1;           // 0..1 -> 64 rows each
    const int warp_n = wid >> 1;          // 0..3 -> 32 cols each
    const int g      = lane >> 2;         // 0..7
    const int ct     = lane & 3;          // 0..3
    const int m0 = blockIdx.x * 128;
    const int n0 = blockIdx.y * 128;

    float acc[4][4][4];
    #pragma unroll
    for (int i = 0; i < 4; i++)
        #pragma unroll
        for (int j = 0; j < 4; j++)
            #pragma unroll
            for (int c = 0; c < 4; c++) acc[i][j][c] = 0.f;

    gemm_issue(sb, 0, m0, n0, tid);
    gemm_issue(sb, 1, m0, n0, tid);
    gemm_issue(sb, 2, m0, n0, tid);

    const int m_lane = warp_m * 64 + g;   // + mt*16 (+8)
    const int n_lane = warp_n * 32 + g;   // + nt*8

    for (int s = 0; s < NSTAGE; s++) {
        if (s + 2 < NSTAGE)      CP_WAIT(2);
        else if (s + 1 < NSTAGE) CP_WAIT(1);
        else                     CP_WAIT(0);
        __syncthreads();
        if (s + 3 < NSTAGE) gemm_issue(sb, s + 3, m0, n0, tid);

        const uint32_t* Ab = As + (s & 3) * A_WORDS;
        const uint32_t* Bb = Bs + (s & 3) * B_WORDS;

        #pragma unroll
        for (int kk = 0; kk < 2; kk++) {
            const int kf = kk * 8 + ct;
            uint32_t a[4][4], b[4][2];
            #pragma unroll
            for (int mt = 0; mt < 4; mt++) {
                int m = m_lane + mt * 16;
                a[mt][0] = Ab[kf * 128 + (m ^ (kf << 3))];
                a[mt][1] = Ab[kf * 128 + ((m + 8) ^ (kf << 3))];
                a[mt][2] = Ab[(kf + 4) * 128 + (m ^ ((kf + 4) << 3))];
                a[mt][3] = Ab[(kf + 4) * 128 + ((m + 8) ^ ((kf + 4) << 3))];
            }
            #pragma unroll
            for (int nt = 0; nt < 4; nt++) {
                int n = n_lane + nt * 8;
                b[nt][0] = Bb[n * 20 + kf];
                b[nt][1] = Bb[n * 20 + kf + 4];
            }
            #pragma unroll
            for (int mt = 0; mt < 4; mt++)
                #pragma unroll
                for (int nt = 0; nt < 4; nt++)
                    mma_tf32(acc[mt][nt], a[mt], b[nt]);
        }
    }

    // epilogue: D[m][n] + b2[n] -> g_h2 (float2 stores)
    #pragma unroll
    for (int nt = 0; nt < 4; nt++) {
        const int n = n0 + warp_n * 32 + nt * 8 + ct * 2;
        const float bx = __ldg(b2 + n), by = __ldg(b2 + n + 1);
        #pragma unroll
        for (int mt = 0; mt < 4; mt++) {
            const int m = m0 + warp_m * 64 + mt * 16 + g;
            float2 v0 = make_float2(acc[mt][nt][0] + bx, acc[mt][nt][1] + by);
            float2 v1 = make_float2(acc[mt][nt][2] + bx, acc[mt][nt][3] + by);
            *reinterpret_cast<float2*>(&g_h2[(size_t)m * EMB + n])       = v0;
            *reinterpret_cast<float2*>(&g_h2[(size_t)(m + 8) * EMB + n]) = v1;
        }
    }
}

// ---------------- K5: BN2 partial stats ----------------
__global__ __launch_bounds__(512) void stats_partial_k() {
    const int e = threadIdx.x;
    const int b = blockIdx.x;
    float s1 = 0.f, s2 = 0.f;
    const float* base = g_h2 + (size_t)b * 128 * EMB + e;
    #pragma unroll 4
    for (int n = 0; n < 128; n++) {
        float v = base[(size_t)n * EMB];
        s1 += v;
        s2 += v * v;
    }
    g_p1[b * EMB + e] = s1;
    g_p2[b * EMB + e] = s2;
}

// ---------------- K6: finalize BN2 ----------------
__global__ __launch_bounds__(512) void stats_final_k(
    const float* __restrict__ g2, const float* __restrict__ beta2)
{
    const int e = threadIdx.x;
    float s1 = 0.f, s2 = 0.f;
    #pragma unroll
    for (int b = 0; b < 64; b++) { s1 += g_p1[b * EMB + e]; s2 += g_p2[b * EMB + e]; }
    float m = s1 * (1.f / (float)N_TOK);
    float v = s2 * (1.f / (float)N_TOK) - m * m;
    float mul = g2[e] * rsqrtf(v + 1e-5f);
    g_mul2[e] = mul;
    g_add2[e] = beta2[e] - mul * m;
}

// ---------------- K7: BN2 apply + gelu -> out ----------------
__global__ __launch_bounds__(256) void final_k(float* __restrict__ out) {
    int idx = blockIdx.x * 256 + threadIdx.x;
    int e = idx & (EMB - 1);
    float x = fmaf(g_mul2[e], g_h2[idx], g_add2[e]);
    out[idx] = gelu_exact(x);
}

// ---------------- launch ----------------
extern "C" void kernel_launch(void* const* d_in, const int* in_sizes, int n_in,
                              void* d_out, int out_size)
{
    const int*   x_t_raw = (const int*)d_in[0];
    const float* W1    = (const float*)d_in[1];
    const float* g1    = (const float*)d_in[3];
    const float* beta1 = (const float*)d_in[4];
    const float* W2    = (const float*)d_in[5];
    const float* b2    = (const float*)d_in[6];
    const float* g2    = (const float*)d_in[7];
    const float* beta2 = (const float*)d_in[8];
    float* out = (float*)d_out;

    cudaFuncSetAttribute(gemm_mma_k, cudaFuncAttributeMaxDynamicSharedMemorySize, GEMM_SMEM);

    detect_k<<<1, 1024>>>(x_t_raw);
    normalize_k<<<N_TOK / 256, 256>>>(x_t_raw);
    hist_k<<<N_TOK / 256, 256>>>();
    gather_bn1_k<<<INTER, 256>>>(W1, g1, beta1);
    round_w2_k<<<(EMB * INTER) / 256, 256>>>(W2);
    gemm_mma_k<<<dim3(N_TOK / 128, EMB / 128), 256, GEMM_SMEM>>>(b2);
    stats_partial_k<<<64, 512>>>();
    stats_final_k<<<1, 512>>>(g2, beta2);
    final_k<<<(N_TOK * EMB) / 256, 256>>>(out);
}

// round 6
// speedup vs baseline: 5.0581x; 1.0418x over previous
#include <cuda_runtime.h>
#include <math.h>
#include <stdint.h>

#define VOCAB 8192
#define N_TOK 8192
#define INTER 4352
#define EMB   512

// ---------------- scratch ----------------
__device__ __align__(16) float g_At[(size_t)INTER * N_TOK];   // A^T: [K][M], tf32-rounded
__device__ __align__(16) float g_W2r[(size_t)EMB * INTER];    // W2 tf32-rounded
__device__ __align__(16) float g_h2[(size_t)N_TOK * EMB];     // h2 pre-BN2: [M][N]
__device__ __align__(16) int   g_cnt[VOCAB];
__device__ __align__(16) int   g_xt[N_TOK];
__device__ int   g_is64;
__device__ __align__(16) float g_p1[64 * EMB];                // per-m-tile BN2 partials
__device__ __align__(16) float g_p2[64 * EMB];
__device__ float g_mul2[EMB];
__device__ float g_add2[EMB];

// ---------------- helpers ----------------
__device__ __forceinline__ float gelu_exact(float x) {
    return 0.5f * x * (1.0f + erff(x * 0.7071067811865476f));
}
__device__ __forceinline__ float rnd_tf32(float x) {
    unsigned u;
    asm("cvt.rna.tf32.f32 %0, %1;" : "=r"(u) : "f"(x));
    return __uint_as_float(u);
}
__device__ __forceinline__ uint32_t smem_u32(const void* p) {
    uint32_t a;
    asm("{ .reg .u64 t; cvta.to.shared.u64 t, %1; cvt.u32.u64 %0, t; }" : "=r"(a) : "l"(p));
    return a;
}
__device__ __forceinline__ void cp_async16(uint32_t dst, const void* src) {
    asm volatile("cp.async.cg.shared.global [%0], [%1], 16;" :: "r"(dst), "l"(src));
}
#define CP_COMMIT() asm volatile("cp.async.commit_group;" ::: "memory")
#define CP_WAIT(n)  asm volatile("cp.async.wait_group %0;" :: "n"(n) : "memory")

__device__ __forceinline__ void mma_tf32(float* d, const uint32_t* a, const uint32_t* b) {
    asm volatile(
        "mma.sync.aligned.m16n8k8.row.col.f32.tf32.tf32.f32 "
        "{%0,%1,%2,%3}, {%4,%5,%6,%7}, {%8,%9}, {%0,%1,%2,%3};"
        : "+f"(d[0]), "+f"(d[1]), "+f"(d[2]), "+f"(d[3])
        : "r"(a[0]), "r"(a[1]), "r"(a[2]), "r"(a[3]), "r"(b[0]), "r"(b[1]));
}

// ---------------- K0a: dtype detect + zero histogram ----------------
__global__ void detect_k(const int* __restrict__ xt_raw) {
    __shared__ int nz;
    if (threadIdx.x == 0) nz = 0;
    __syncthreads();
    int any = 0;
    for (int i = threadIdx.x; i < N_TOK / 2; i += 1024)
        any |= (xt_raw[2 * i + 1] != 0);
    if (any) atomicOr(&nz, 1);
    #pragma unroll
    for (int r = 0; r < VOCAB / 1024; r++)
        g_cnt[r * 1024 + threadIdx.x] = 0;
    __syncthreads();
    if (threadIdx.x == 0) g_is64 = (nz == 0);
}

// ---------------- K0b: normalize indices + histogram ----------------
__global__ void norm_hist_k(const int* __restrict__ xt_raw) {
    int n = blockIdx.x * 256 + threadIdx.x;
    int v = g_is64 ? xt_raw[2 * n] : xt_raw[n];
    g_xt[n] = v;
    atomicAdd(&g_cnt[v], 1);
}

// ---------------- K3: fused gather + BN1 + gelu -> At[k][m] (tf32-rounded) -------
__global__ __launch_bounds__(256) void gather_bn1_k(
    const float* __restrict__ W1,
    const float* __restrict__ g1, const float* __restrict__ beta1)
{
    __shared__ __align__(16) float row[VOCAB];
    __shared__ float red[16];
    const int i   = blockIdx.x;
    const int tid = threadIdx.x;
    const float* wrow = W1 + (size_t)i * VOCAB;

    float s1 = 0.f, s2 = 0.f;
    for (int idx = tid; idx < VOCAB / 4; idx += 256) {
        float4 w = reinterpret_cast<const float4*>(wrow)[idx];
        int4   c = reinterpret_cast<const int4*>(g_cnt)[idx];
        reinterpret_cast<float4*>(row)[idx] = w;
        s1 += (float)c.x * w.x + (float)c.y * w.y + (float)c.z * w.z + (float)c.w * w.w;
        s2 += (float)c.x * w.x * w.x + (float)c.y * w.y * w.y
            + (float)c.z * w.z * w.z + (float)c.w * w.w * w.w;
    }
    #pragma unroll
    for (int o = 16; o > 0; o >>= 1) {
        s1 += __shfl_down_sync(0xffffffffu, s1, o);
        s2 += __shfl_down_sync(0xffffffffu, s2, o);
    }
    if ((tid & 31) == 0) { red[tid >> 5] = s1; red[8 + (tid >> 5)] = s2; }
    __syncthreads();

    float t1 = 0.f, t2 = 0.f;
    #pragma unroll
    for (int w = 0; w < 8; w++) { t1 += red[w]; t2 += red[8 + w]; }
    const float mean = t1 * (1.f / (float)N_TOK);
    const float var  = t2 * (1.f / (float)N_TOK) - mean * mean;
    const float mul  = g1[i] * rsqrtf(var + 1e-5f);
    const float beta = beta1[i];

    float* dst = g_At + (size_t)i * N_TOK;
    #pragma unroll 4
    for (int n = tid; n < N_TOK; n += 256) {
        int c = g_xt[n];
        float x = (row[c] - mean) * mul + beta;
        dst[n] = rnd_tf32(gelu_exact(x));
    }
}

// ---------------- K3b: round W2 to tf32 ----------------
__global__ void round_w2_k(const float* __restrict__ W2) {
    int i = blockIdx.x * 256 + threadIdx.x;
    g_W2r[i] = rnd_tf32(W2[i]);
}

// ---------------- K4: mma.sync tf32 GEMM + fused BN2 partial stats ----------------
// BM=128, BN=256, BK=16; 256 thr = 8 warps (2x4), warp tile 64x64; 4-stage cp.async
#define BK 16
#define BN 256
#define NSTAGE (INTER / BK)                 // 272
#define A_WORDS (BK * 128)                  // 2048
#define B_WORDS (BN * 20)                   // 5120 (stride-20 rows, pad 4)
#define A_STAGE_BYTES (A_WORDS * 4)         // 8192
#define B_STAGE_BYTES (B_WORDS * 4)         // 20480
#define B_BASE_BYTES  (4 * A_STAGE_BYTES)
#define GEMM_SMEM (4 * (A_STAGE_BYTES + B_STAGE_BYTES))   // 114688

__device__ __forceinline__ void gemm_issue(uint32_t sb, int s, int m0, int n0, int tid) {
    const int k0  = s * BK;
    const int buf = s & 3;
    // A tile: 512 float4 (16 k-rows x 128 m), 2/thread, XOR swizzle
    #pragma unroll
    for (int t = 0; t < 2; t++) {
        int idx = tid + t * 256;
        int k = idx >> 5;
        int mq = (idx & 31) << 2;
        const float* src = g_At + (size_t)(k0 + k) * N_TOK + m0 + mq;
        uint32_t word = (uint32_t)(k * 128 + (mq ^ (k << 3)));
        cp_async16(sb + buf * A_STAGE_BYTES + (word << 2), src);
    }
    // B tile: 1024 float4 (256 n-rows x 16 k), 4/thread, stride-20 rows
    #pragma unroll
    for (int t = 0; t < 4; t++) {
        int idx = tid + t * 256;
        int n = idx >> 2;
        int kq = (idx & 3) << 2;
        const float* src = g_W2r + (size_t)(n0 + n) * INTER + k0 + kq;
        uint32_t word = (uint32_t)(n * 20 + kq);
        cp_async16(sb + B_BASE_BYTES + buf * B_STAGE_BYTES + (word << 2), src);
    }
    CP_COMMIT();
}

__global__ __launch_bounds__(256, 1) void gemm_mma_k(const float* __restrict__ b2) {
    extern __shared__ __align__(16) char smem[];
    const uint32_t sb = smem_u32(smem);
    const uint32_t* As = reinterpret_cast<const uint32_t*>(smem);
    const uint32_t* Bs = reinterpret_cast<const uint32_t*>(smem + B_BASE_BYTES);

    const int tid    = threadIdx.x;
    const int lane   = tid & 31;
    const int wid    = tid >> 5;
    const int warp_m = wid & 1;           // 0..1 -> 64 rows
    const int warp_n = wid >> 1;          // 0..3 -> 64 cols
    const int g      = lane >> 2;         // 0..7
    const int ct     = lane & 3;          // 0..3
    const int m0 = blockIdx.x * 128;
    const int n0 = blockIdx.y * BN;

    float acc[4][8][4];
    #pragma unroll
    for (int i = 0; i < 4; i++)
        #pragma unroll
        for (int j = 0; j < 8; j++)
            #pragma unroll
            for (int c = 0; c < 4; c++) acc[i][j][c] = 0.f;

    gemm_issue(sb, 0, m0, n0, tid);
    gemm_issue(sb, 1, m0, n0, tid);
    gemm_issue(sb, 2, m0, n0, tid);

    const int m_lane = warp_m * 64 + g;
    const int n_lane = warp_n * 64 + g;

    for (int s = 0; s < NSTAGE; s++) {
        if (s + 2 < NSTAGE)      CP_WAIT(2);
        else if (s + 1 < NSTAGE) CP_WAIT(1);
        else                     CP_WAIT(0);
        __syncthreads();
        if (s + 3 < NSTAGE) gemm_issue(sb, s + 3, m0, n0, tid);

        const uint32_t* Ab = As + (s & 3) * A_WORDS;
        const uint32_t* Bb = Bs + (s & 3) * B_WORDS;

        #pragma unroll
        for (int kk = 0; kk < 2; kk++) {
            const int kf = kk * 8 + ct;
            uint32_t a[4][4], b[8][2];
            #pragma unroll
            for (int mt = 0; mt < 4; mt++) {
                int m = m_lane + mt * 16;
                a[mt][0] = Ab[kf * 128 + (m ^ (kf << 3))];
                a[mt][1] = Ab[kf * 128 + ((m + 8) ^ (kf << 3))];
                a[mt][2] = Ab[(kf + 4) * 128 + (m ^ ((kf + 4) << 3))];
                a[mt][3] = Ab[(kf + 4) * 128 + ((m + 8) ^ ((kf + 4) << 3))];
            }
            #pragma unroll
            for (int nt = 0; nt < 8; nt++) {
                int n = n_lane + nt * 8;
                b[nt][0] = Bb[n * 20 + kf];
                b[nt][1] = Bb[n * 20 + kf + 4];
            }
            #pragma unroll
            for (int mt = 0; mt < 4; mt++)
                #pragma unroll
                for (int nt = 0; nt < 8; nt++)
                    mma_tf32(acc[mt][nt], a[mt], b[nt]);
        }
    }

    // ---- epilogue: h2 = acc + bias (float2 stores) + deterministic BN2 partials ----
    float* sbuf = reinterpret_cast<float*>(smem);   // [2][BN][2] floats = 4 KB (buf0 free)
    __syncthreads();                                 // all warps done reading smem

    #pragma unroll
    for (int nt = 0; nt < 8; nt++) {
        const int ncol = warp_n * 64 + nt * 8 + ct * 2;   // local col (x), +1 (y)
        const int n = n0 + ncol;
        const float bx = __ldg(b2 + n), by = __ldg(b2 + n + 1);
        float sx1 = 0.f, sx2 = 0.f, sy1 = 0.f, sy2 = 0.f;
        #pragma unroll
        for (int mt = 0; mt < 4; mt++) {
            const int m = m0 + warp_m * 64 + mt * 16 + g;
            float v00 = acc[mt][nt][0] + bx, v01 = acc[mt][nt][1] + by;
            float v10 = acc[mt][nt][2] + bx, v11 = acc[mt][nt][3] + by;
            *reinterpret_cast<float2*>(&g_h2[(size_t)m * EMB + n])       = make_float2(v00, v01);
            *reinterpret_cast<float2*>(&g_h2[(size_t)(m + 8) * EMB + n]) = make_float2(v10, v11);
            sx1 += v00 + v10; sx2 += v00 * v00 + v10 * v10;
            sy1 += v01 + v11; sy2 += v01 * v01 + v11 * v11;
        }
        // reduce over g (lane bits 2..4): fixed tree -> deterministic
        #pragma unroll
        for (int o = 4; o <= 16; o <<= 1) {
            sx1 += __shfl_xor_sync(0xffffffffu, sx1, o);
            sx2 += __shfl_xor_sync(0xffffffffu, sx2, o);
            sy1 += __shfl_xor_sync(0xffffffffu, sy1, o);
            sy2 += __shfl_xor_sync(0xffffffffu, sy2, o);
        }
        if (g == 0) {   // lanes 0..3 hold warp totals (64 rows)
            float* p = sbuf + ((warp_m * BN + ncol) << 1);
            p[0] = sx1; p[1] = sx2; p[2] = sy1; p[3] = sy2;
        }
    }
    __syncthreads();
    // combine the two warp_m halves: 256 threads, one column each
    {
        const int col = tid;
        float p1 = sbuf[(col << 1)] + sbuf[((BN + col) << 1)];
        float p2 = sbuf[(col << 1) + 1] + sbuf[((BN + col) << 1) + 1];
        g_p1[blockIdx.x * EMB + n0 + col] = p1;
        g_p2[blockIdx.x * EMB + n0 + col] = p2;
    }
}

// ---------------- K6: finalize BN2 ----------------
__global__ __launch_bounds__(512) void stats_final_k(
    const float* __restrict__ g2, const float* __restrict__ beta2)
{
    const int e = threadIdx.x;
    float s1 = 0.f, s2 = 0.f;
    #pragma unroll
    for (int b = 0; b < 64; b++) { s1 += g_p1[b * EMB + e]; s2 += g_p2[b * EMB + e]; }
    float m = s1 * (1.f / (float)N_TOK);
    float v = s2 * (1.f / (float)N_TOK) - m * m;
    float mul = g2[e] * rsqrtf(v + 1e-5f);
    g_mul2[e] = mul;
    g_add2[e] = beta2[e] - mul * m;
}

// ---------------- K7: BN2 apply + gelu -> out ----------------
__global__ __launch_bounds__(256) void final_k(float* __restrict__ out) {
    int idx = blockIdx.x * 256 + threadIdx.x;
    int e = idx & (EMB - 1);
    float x = fmaf(g_mul2[e], g_h2[idx], g_add2[e]);
    out[idx] = gelu_exact(x);
}

// ---------------- launch ----------------
extern "C" void kernel_launch(void* const* d_in, const int* in_sizes, int n_in,
                              void* d_out, int out_size)
{
    const int*   x_t_raw = (const int*)d_in[0];
    const float* W1    = (const float*)d_in[1];
    const float* g1    = (const float*)d_in[3];
    const float* beta1 = (const float*)d_in[4];
    const float* W2    = (const float*)d_in[5];
    const float* b2    = (const float*)d_in[6];
    const float* g2    = (const float*)d_in[7];
    const float* beta2 = (const float*)d_in[8];
    float* out = (float*)d_out;

    cudaFuncSetAttribute(gemm_mma_k, cudaFuncAttributeMaxDynamicSharedMemorySize, GEMM_SMEM);

    round_w2_k<<<(EMB * INTER) / 256, 256>>>(W2);
    detect_k<<<1, 1024>>>(x_t_raw);
    norm_hist_k<<<N_TOK / 256, 256>>>(x_t_raw);
    gather_bn1_k<<<INTER, 256>>>(W1, g1, beta1);
    gemm_mma_k<<<dim3(N_TOK / 128, EMB / BN), 256, GEMM_SMEM>>>(b2);
    stats_final_k<<<1, 512>>>(g2, beta2);
    final_k<<<(N_TOK * EMB) / 256, 256>>>(out);
}